// round 9
// baseline (speedup 1.0000x reference)
#include <cuda_runtime.h>

#define NSTATES 128
#define HALF    64

static __device__ __forceinline__ float warp_max(float v) {
#pragma unroll
    for (int d = 16; d; d >>= 1) v = fmaxf(v, __shfl_xor_sync(0xffffffffu, v, d));
    return v;
}
static __device__ __forceinline__ float warp_sum(float v) {
#pragma unroll
    for (int d = 16; d; d >>= 1) v += __shfl_xor_sync(0xffffffffu, v, d);
    return v;
}

// One scan step (split-K by 2): thread (j,h) computes the h-th half of
//   q[j] = sum_i p[i]*T[i][j]
// halves combined via shfl_xor(.,1) (partner = adjacent lane), then
//   p'[j] = q[j] * exp(obs[t,j])   (optionally rescaled).
// APPLY: multiply q by 1/max (block max computed one step earlier), add log(max) to C.
// CMAX : compute block max of new p into wred[] for the next step's APPLY.
template <bool APPLY, bool CMAX>
static __device__ __forceinline__ float crf_step(
    const unsigned long long (&tc)[32],
    const float* __restrict__ pin, float* __restrict__ pout,
    float obsv, float& C, float* wred,
    int warp, int lane, int j, int h)
{
    float eo = __expf(obsv);

    unsigned long long a0 = 0ull, a1 = 0ull, a2 = 0ull, a3 = 0ull;
    const ulonglong2* pv = reinterpret_cast<const ulonglong2*>(pin + (h << 6));
#pragma unroll
    for (int k = 0; k < 16; k += 2) {
        ulonglong2 pa = pv[k];      // p[h*64 + 4k   .. +3]  (2-address broadcast LDS.128)
        ulonglong2 pb = pv[k + 1];  // p[h*64 + 4k+4 .. +7]
        asm("fma.rn.f32x2 %0, %1, %2, %0;" : "+l"(a0) : "l"(pa.x), "l"(tc[2 * k + 0]));
        asm("fma.rn.f32x2 %0, %1, %2, %0;" : "+l"(a1) : "l"(pa.y), "l"(tc[2 * k + 1]));
        asm("fma.rn.f32x2 %0, %1, %2, %0;" : "+l"(a2) : "l"(pb.x), "l"(tc[2 * k + 2]));
        asm("fma.rn.f32x2 %0, %1, %2, %0;" : "+l"(a3) : "l"(pb.y), "l"(tc[2 * k + 3]));
    }
    asm("add.rn.f32x2 %0, %0, %1;" : "+l"(a0) : "l"(a2));
    asm("add.rn.f32x2 %0, %0, %1;" : "+l"(a1) : "l"(a3));
    asm("add.rn.f32x2 %0, %0, %1;" : "+l"(a0) : "l"(a1));
    float qx, qy;
    asm("mov.b64 {%0, %1}, %2;" : "=f"(qx), "=f"(qy) : "l"(a0));
    float q = qx + qy;

    // Combine the two halves of output j: partner lane is lane^1.
    q += __shfl_xor_sync(0xffffffffu, q, 1);

    if (APPLY) {
        float mx = fmaxf(fmaxf(fmaxf(wred[0], wred[1]), fmaxf(wred[2], wred[3])),
                         fmaxf(fmaxf(wred[4], wred[5]), fmaxf(wred[6], wred[7])));
        q = q * __fdividef(1.0f, mx);
        C += __logf(mx);
    }

    float pn = q * eo;
    if (h == 0) pout[j] = pn;   // even lanes write 16 consecutive floats: conflict-free

    if (CMAX) {
        float m = warp_max(pn);
        if (lane == 0) wred[warp] = m;
    }
    __syncthreads();
    return pn;
}

__global__ void __launch_bounds__(256, 1)
crf_forward_kernel(const float* __restrict__ obs,
                   const float* __restrict__ logA,
                   float* __restrict__ out, int T)
{
    const int b    = blockIdx.x;
    const int t    = threadIdx.x;
    const int h    = t & 1;        // which half of the inner product
    const int j    = t >> 1;       // output state
    const int warp = t >> 5;
    const int lane = t & 31;

    __shared__ __align__(16) float psh[2][NSTATES];
    __shared__ float wred[8];

    // Half-column of exp(A) in registers: i in [h*64, h*64+64), packed as f32x2 pairs.
    unsigned long long tc[32];
#pragma unroll
    for (int m = 0; m < 32; ++m) {
        float2 t2;
        t2.x = expf(logA[(h * HALF + 2 * m + 0) * NSTATES + j]);
        t2.y = expf(logA[(h * HALF + 2 * m + 1) * NSTATES + j]);
        tc[m] = *reinterpret_cast<unsigned long long*>(&t2);
    }

    const float* obj = obs + (size_t)b * ((size_t)T * NSTATES) + j;

    // ---- t = 0: fv0 = obs[:,0,:], p = exp(fv0 - m0), C = m0 ----
    float o0 = obj[0];
    float m0 = warp_max(o0);
    if (lane == 0) wred[warp] = m0;
    __syncthreads();
    m0 = fmaxf(fmaxf(fmaxf(wred[0], wred[1]), fmaxf(wred[2], wred[3])),
               fmaxf(fmaxf(wred[4], wred[5]), fmaxf(wred[6], wred[7])));
    float C = m0;
    if (h == 0) psh[0][j] = __expf(o0 - m0);
    __syncthreads();

    // ---- prefetch obs for t = 1..4 ----
    float f0 = obj[1 * NSTATES];
    float f1 = obj[2 * NSTATES];
    float f2 = obj[3 * NSTATES];
    float f3 = obj[4 * NSTATES];

    const int offmax = (T - 1) * NSTATES;
    int off = 5 * NSTATES;  // next element to prefetch (t=5)

    const int G   = (T - 1) >> 2;   // full groups of 4 steps
    const int rem = (T - 1) & 3;
    float pn = 0.0f;

    for (int g = 0; g < G; ++g) {
        float o;
        // slot A: t = 4g+1 (plain)       psh0 -> psh1
        o = f0; f0 = __ldg(obj + (off < offmax ? off : offmax)); off += NSTATES;
        pn = crf_step<false, false>(tc, psh[0], psh[1], o, C, wred, warp, lane, j, h);
        // slot B: t = 4g+2 (plain)       psh1 -> psh0
        o = f1; f1 = __ldg(obj + (off < offmax ? off : offmax)); off += NSTATES;
        pn = crf_step<false, false>(tc, psh[1], psh[0], o, C, wred, warp, lane, j, h);
        // slot C: t = 4g+3 (compute max) psh0 -> psh1
        o = f2; f2 = __ldg(obj + (off < offmax ? off : offmax)); off += NSTATES;
        pn = crf_step<false, true >(tc, psh[0], psh[1], o, C, wred, warp, lane, j, h);
        // slot D: t = 4g+4 (apply scale) psh1 -> psh0
        o = f3; f3 = __ldg(obj + (off < offmax ? off : offmax)); off += NSTATES;
        pn = crf_step<true,  false>(tc, psh[1], psh[0], o, C, wred, warp, lane, j, h);
    }

    // ---- tail steps (for T=4096: rem = 3) ----
    if (rem > 0) pn = crf_step<false, false>(tc, psh[0], psh[1], f0, C, wred, warp, lane, j, h);
    if (rem > 1) pn = crf_step<false, false>(tc, psh[1], psh[0], f1, C, wred, warp, lane, j, h);
    if (rem > 2) pn = crf_step<false, false>(tc, psh[0], psh[1], f2, C, wred, warp, lane, j, h);

    // ---- final: out[b] = -(C + log(sum_j p[j])) ----
    // pn is duplicated across the lane pair; count only h==0 lanes.
    float s = warp_sum(h == 0 ? pn : 0.0f);
    if (lane == 0) wred[warp] = s;
    __syncthreads();
    if (t == 0) {
        float tot = (wred[0] + wred[1]) + (wred[2] + wred[3])
                  + (wred[4] + wred[5]) + (wred[6] + wred[7]);
        out[b] = -(C + logf(tot));
    }
}

extern "C" void kernel_launch(void* const* d_in, const int* in_sizes, int n_in,
                              void* d_out, int out_size)
{
    const float* obs  = (const float*)d_in[0];   // [B, T, S] fp32
    const float* logA = (const float*)d_in[1];   // [S, S] fp32
    float* out = (float*)d_out;                  // [B] fp32

    const int B = out_size;                      // 64
    const int T = in_sizes[0] / (B * NSTATES);   // 4096

    crf_forward_kernel<<<B, 2 * NSTATES>>>(obs, logA, out, T);
}

// round 10
// speedup vs baseline: 1.2971x; 1.2971x over previous
#include <cuda_runtime.h>

#define NSTATES 128

#define LDSV2(x, y, a) \
    asm volatile("ld.shared.v2.u64 {%0,%1}, [%2];" : "=l"(x), "=l"(y) : "r"(a))
#define FMA2(acc, p, t) \
    asm volatile("fma.rn.f32x2 %0, %1, %2, %0;" : "+l"(acc) : "l"(p), "l"(t))
#define ADD2(acc, b) \
    asm volatile("add.rn.f32x2 %0, %0, %1;" : "+l"(acc) : "l"(b))

static __device__ __forceinline__ float warp_max(float v) {
#pragma unroll
    for (int d = 16; d; d >>= 1) v = fmaxf(v, __shfl_xor_sync(0xffffffffu, v, d));
    return v;
}
static __device__ __forceinline__ float warp_sum(float v) {
#pragma unroll
    for (int d = 16; d; d >>= 1) v += __shfl_xor_sync(0xffffffffu, v, d);
    return v;
}

// One scan step: q[j] = sum_i p[i]*T[i][j];  p'[j] = q[j]*exp(obs[t,j]).
// MODE 0: plain.  MODE 1: also compute block max of p' into wred (for renorm).
// MODE 2: apply renorm (q *= 1/max from the previous step's MODE-1), C += log(max).
// Inner product is a hand-pipelined volatile-asm sequence: 6 LDS.128 in flight,
// fixed interleave with the FFMA2 stream, so ptxas cannot hoist-then-spill.
template <int MODE>
static __device__ __forceinline__ float crf_step(
    const unsigned long long (&tc)[64],
    unsigned int pin_a, float* __restrict__ pout,
    float obsv, float& C, float* wred, int warp, int lane, int j)
{
    float eo = __expf(obsv);

    unsigned long long v[12];
    unsigned long long a[4] = {0ull, 0ull, 0ull, 0ull};

    LDSV2(v[0],  v[1],  pin_a + 0);
    LDSV2(v[2],  v[3],  pin_a + 16);
    LDSV2(v[4],  v[5],  pin_a + 32);
    LDSV2(v[6],  v[7],  pin_a + 48);
    LDSV2(v[8],  v[9],  pin_a + 64);
    LDSV2(v[10], v[11], pin_a + 80);
#pragma unroll
    for (int k = 0; k < 32; ++k) {
        const int s = (k % 6) * 2;        // static after full unroll
        const int u = (k & 1) * 2;        // alternate accumulator pair
        FMA2(a[u],     v[s],     tc[2 * k]);
        FMA2(a[u + 1], v[s + 1], tc[2 * k + 1]);
        if (k < 26) LDSV2(v[s], v[s + 1], pin_a + (k + 6) * 16);
    }
    ADD2(a[0], a[2]);
    ADD2(a[1], a[3]);
    ADD2(a[0], a[1]);
    float qx, qy;
    asm("mov.b64 {%0, %1}, %2;" : "=f"(qx), "=f"(qy) : "l"(a[0]));
    float q = qx + qy;

    if (MODE == 2) {
        float4 w = *reinterpret_cast<const float4*>(wred);
        float mx = fmaxf(fmaxf(w.x, w.y), fmaxf(w.z, w.w));
        q = q * __fdividef(1.0f, mx);
        C += __logf(mx);
    }

    float pn = q * eo;
    pout[j] = pn;

    if (MODE == 1) {
        float m = warp_max(pn);
        if (lane == 0) wred[warp] = m;
    }
    __syncthreads();
    return pn;
}

__global__ void __launch_bounds__(128, 1)
crf_forward_kernel(const float* __restrict__ obs,
                   const float* __restrict__ logA,
                   float* __restrict__ out, int T)
{
    const int b    = blockIdx.x;
    const int j    = threadIdx.x;
    const int warp = j >> 5;
    const int lane = j & 31;

    __shared__ __align__(16) float psh[2][NSTATES];
    __shared__ __align__(16) float wred[4];

    // Column j of exp(A) in registers, packed as (i even, i odd) f32x2 pairs.
    unsigned long long tc[64];
#pragma unroll
    for (int m = 0; m < 64; ++m) {
        float2 t2;
        t2.x = expf(logA[(2 * m + 0) * NSTATES + j]);
        t2.y = expf(logA[(2 * m + 1) * NSTATES + j]);
        tc[m] = *reinterpret_cast<unsigned long long*>(&t2);
    }

    const unsigned int p0a = (unsigned int)__cvta_generic_to_shared(psh[0]);
    const unsigned int p1a = (unsigned int)__cvta_generic_to_shared(psh[1]);

    const float* obj = obs + (size_t)b * ((size_t)T * NSTATES) + j;

    // ---- t = 0: fv0 = obs[:,0,:], p = exp(fv0 - m0), C = m0 ----
    float o0 = obj[0];
    float m0 = warp_max(o0);
    if (lane == 0) wred[warp] = m0;
    __syncthreads();
    m0 = fmaxf(fmaxf(wred[0], wred[1]), fmaxf(wred[2], wred[3]));
    float C = m0;
    psh[0][j] = __expf(o0 - m0);
    __syncthreads();

    // ---- prefetch ring: obs for t = 1..4 ----
    float f0 = obj[1 * NSTATES];
    float f1 = obj[2 * NSTATES];
    float f2 = obj[3 * NSTATES];
    float f3 = obj[4 * NSTATES];

    const int offmax = (T - 1) * NSTATES;
    int off = 5 * NSTATES;

    const int G   = (T - 1) >> 3;   // full groups of 8 steps (renorm once per group)
    const int rem = (T - 1) & 7;    // for T=4096: rem = 7
    float pn = 0.0f;

#define PF(fr) do { fr = __ldg(obj + (off < offmax ? off : offmax)); off += NSTATES; } while (0)

    for (int g = 0; g < G; ++g) {
        float o;
        o = f0; PF(f0); pn = crf_step<0>(tc, p0a, psh[1], o, C, wred, warp, lane, j);
        o = f1; PF(f1); pn = crf_step<0>(tc, p1a, psh[0], o, C, wred, warp, lane, j);
        o = f2; PF(f2); pn = crf_step<0>(tc, p0a, psh[1], o, C, wred, warp, lane, j);
        o = f3; PF(f3); pn = crf_step<0>(tc, p1a, psh[0], o, C, wred, warp, lane, j);
        o = f0; PF(f0); pn = crf_step<0>(tc, p0a, psh[1], o, C, wred, warp, lane, j);
        o = f1; PF(f1); pn = crf_step<0>(tc, p1a, psh[0], o, C, wred, warp, lane, j);
        o = f2; PF(f2); pn = crf_step<1>(tc, p0a, psh[1], o, C, wred, warp, lane, j);
        o = f3; PF(f3); pn = crf_step<2>(tc, p1a, psh[0], o, C, wred, warp, lane, j);
    }

    // ---- tail (rem <= 7 plain steps; drift stays well inside fp32 range) ----
    {
        float o;
        if (rem > 0) { o = f0; PF(f0); pn = crf_step<0>(tc, p0a, psh[1], o, C, wred, warp, lane, j); }
        if (rem > 1) { o = f1; PF(f1); pn = crf_step<0>(tc, p1a, psh[0], o, C, wred, warp, lane, j); }
        if (rem > 2) { o = f2; PF(f2); pn = crf_step<0>(tc, p0a, psh[1], o, C, wred, warp, lane, j); }
        if (rem > 3) { o = f3; PF(f3); pn = crf_step<0>(tc, p1a, psh[0], o, C, wred, warp, lane, j); }
        if (rem > 4) { o = f0;         pn = crf_step<0>(tc, p0a, psh[1], o, C, wred, warp, lane, j); }
        if (rem > 5) { o = f1;         pn = crf_step<0>(tc, p1a, psh[0], o, C, wred, warp, lane, j); }
        if (rem > 6) { o = f2;         pn = crf_step<0>(tc, p0a, psh[1], o, C, wred, warp, lane, j); }
    }
#undef PF

    // ---- final: out[b] = -(C + log(sum_j p[j])) ----
    float s = warp_sum(pn);
    if (lane == 0) wred[warp] = s;
    __syncthreads();
    if (j == 0) {
        float tot = (wred[0] + wred[1]) + (wred[2] + wred[3]);
        out[b] = -(C + logf(tot));
    }
}

extern "C" void kernel_launch(void* const* d_in, const int* in_sizes, int n_in,
                              void* d_out, int out_size)
{
    const float* obs  = (const float*)d_in[0];   // [B, T, S] fp32
    const float* logA = (const float*)d_in[1];   // [S, S] fp32
    float* out = (float*)d_out;                  // [B] fp32

    const int B = out_size;                      // 64
    const int T = in_sizes[0] / (B * NSTATES);   // 4096

    crf_forward_kernel<<<B, NSTATES>>>(obs, logA, out, T);
}